// round 6
// baseline (speedup 1.0000x reference)
#include <cuda_runtime.h>

#define N_NODES 100000
#define N_EDGES 1600000
#define F_IN  64
#define F_HID 64
#define F_OUT 32
#define SCAN_B 1024
#define NCHUNK ((N_NODES + SCAN_B - 1) / SCAN_B)

// ---------------- scratch (static device globals; no runtime allocation) ---
__device__ int   g_is64;                // 1 if edge_index is int64, 0 if int32
__device__ int   g_cnt[N_NODES];        // in-degree (w/o self loop)
__device__ int   g_rowstart[N_NODES];   // CSR row offsets
__device__ int   g_cursor[N_NODES];     // placement cursors
__device__ int   g_col[N_EDGES];        // CSR column (src) indices
__device__ int   g_bsum[NCHUNK];        // scan block partials
__device__ float g_dinv[N_NODES];       // deg^{-1/2}
__device__ float g_xs[(size_t)N_NODES * F_HID];   // dinv * (x @ W1)
__device__ float g_h [(size_t)N_NODES * F_HID];   // relu(layer1 out)
__device__ float g_hs[(size_t)N_NODES * F_OUT];   // dinv * (h @ W2)
__device__ float g_pool[F_OUT];

// ---------------- dtype sniff: int64 edge_index has zero odd 32-bit words --
__global__ void k_detect(const unsigned int* __restrict__ e) {
    unsigned int acc = 0;
    for (int i = threadIdx.x; i < 2048; i += 32)
        if (i & 1) acc |= e[i];
    #pragma unroll
    for (int o = 16; o; o >>= 1) acc |= __shfl_xor_sync(0xffffffffu, acc, o);
    if (threadIdx.x == 0) g_is64 = (acc == 0u) ? 1 : 0;
}

// ---------------- init ----------------
__global__ void k_zero() {
    int i = blockIdx.x * blockDim.x + threadIdx.x;
    if (i < N_NODES) g_cnt[i] = 0;
    if (i < F_OUT)   g_pool[i] = 0.f;
}

// ---------------- degree count over dst ----------------
__global__ void k_count(const void* __restrict__ eiv) {
    int e = blockIdx.x * blockDim.x + threadIdx.x;
    if (e >= N_EDGES) return;
    int d;
    if (g_is64) d = (int)((const long long*)eiv)[N_EDGES + e];
    else        d = ((const int*)eiv)[N_EDGES + e];
    atomicAdd(&g_cnt[d], 1);
}

// ---------------- exclusive scan (3 kernels) ----------------
__global__ void k_scan_partial() {
    __shared__ int s[SCAN_B];
    int t = threadIdx.x;
    int idx = blockIdx.x * SCAN_B + t;
    int v = (idx < N_NODES) ? g_cnt[idx] : 0;
    s[t] = v;
    __syncthreads();
    #pragma unroll
    for (int off = 1; off < SCAN_B; off <<= 1) {
        int x = (t >= off) ? s[t - off] : 0;
        __syncthreads();
        s[t] += x;
        __syncthreads();
    }
    if (idx < N_NODES) g_rowstart[idx] = s[t] - v;   // exclusive
    if (t == SCAN_B - 1) g_bsum[blockIdx.x] = s[t];
}

__global__ void k_scan_bsum() {
    if (threadIdx.x == 0) {
        int run = 0;
        for (int i = 0; i < NCHUNK; i++) { int v = g_bsum[i]; g_bsum[i] = run; run += v; }
    }
}

__global__ void k_scan_add() {
    int i = blockIdx.x * blockDim.x + threadIdx.x;
    if (i >= N_NODES) return;
    int rs = g_rowstart[i] + g_bsum[i >> 10];
    g_rowstart[i] = rs;
    g_cursor[i]   = rs;
    g_dinv[i] = rsqrtf((float)(g_cnt[i] + 1));       // +1 self loop
}

// ---------------- CSR placement ----------------
__global__ void k_place(const void* __restrict__ eiv) {
    int e = blockIdx.x * blockDim.x + threadIdx.x;
    if (e >= N_EDGES) return;
    int s, d;
    if (g_is64) {
        const long long* ei = (const long long*)eiv;
        s = (int)ei[e];
        d = (int)ei[N_EDGES + e];
    } else {
        const int* ei = (const int*)eiv;
        s = ei[e];
        d = ei[N_EDGES + e];
    }
    int pos = atomicAdd(&g_cursor[d], 1);
    g_col[pos] = s;
}

// ---------------- GEMM1: xs = dinv * (x @ W1)   [N,64]@[64,64] ----------------
__global__ void k_gemm1(const float* __restrict__ x, const float* __restrict__ W1) {
    __shared__ float Ws[64 * 64];
    __shared__ float Xs[4][64];
    int t = threadIdx.x;
    for (int i = t; i < 64 * 64; i += 256) Ws[i] = W1[i];
    __syncthreads();
    int r = t >> 6, c = t & 63;
    int ntiles = (N_NODES + 3) / 4;
    for (int tile = blockIdx.x; tile < ntiles; tile += gridDim.x) {
        int row0 = tile * 4;
        {
            int row = row0 + r;
            Xs[r][c] = (row < N_NODES) ? x[(size_t)row * 64 + c] : 0.f;
        }
        __syncthreads();
        float acc = 0.f;
        #pragma unroll
        for (int k = 0; k < 64; k++)
            acc = fmaf(Xs[r][k], Ws[k * 64 + c], acc);
        int row = row0 + r;
        if (row < N_NODES) g_xs[(size_t)row * 64 + c] = g_dinv[row] * acc;
        __syncthreads();
    }
}

// ---------------- aggregate layer 1 (warp per node) ----------------
__global__ void k_agg1(const float* __restrict__ b1) {
    int gw = (blockIdx.x * blockDim.x + threadIdx.x) >> 5;
    if (gw >= N_NODES) return;
    int lane = threadIdx.x & 31;
    int start = g_rowstart[gw];
    int cnt   = g_cnt[gw];
    float a0 = g_xs[(size_t)gw * 64 + lane];         // self loop
    float a1 = g_xs[(size_t)gw * 64 + lane + 32];
    for (int e = 0; e < cnt; e++) {
        int j = g_col[start + e];
        a0 += __ldg(&g_xs[(size_t)j * 64 + lane]);
        a1 += __ldg(&g_xs[(size_t)j * 64 + lane + 32]);
    }
    float di = g_dinv[gw];
    g_h[(size_t)gw * 64 + lane]      = fmaxf(fmaf(di, a0, b1[lane]),      0.f);
    g_h[(size_t)gw * 64 + lane + 32] = fmaxf(fmaf(di, a1, b1[lane + 32]), 0.f);
}

// ---------------- GEMM2: hs = dinv * (h @ W2)   [N,64]@[64,32] ----------------
__global__ void k_gemm2(const float* __restrict__ W2) {
    __shared__ float Ws[64 * 32];
    __shared__ float Hs[8][64];
    int t = threadIdx.x;
    for (int i = t; i < 64 * 32; i += 256) Ws[i] = W2[i];
    __syncthreads();
    int r = t >> 5, c = t & 31;
    int ntiles = (N_NODES + 7) / 8;
    for (int tile = blockIdx.x; tile < ntiles; tile += gridDim.x) {
        int row0 = tile * 8;
        for (int i = t; i < 8 * 64; i += 256) {
            int rr = i >> 6, cc = i & 63;
            int row = row0 + rr;
            Hs[rr][cc] = (row < N_NODES) ? g_h[(size_t)row * 64 + cc] : 0.f;
        }
        __syncthreads();
        float acc = 0.f;
        #pragma unroll
        for (int k = 0; k < 64; k++)
            acc = fmaf(Hs[r][k], Ws[k * 32 + c], acc);
        int row = row0 + r;
        if (row < N_NODES) g_hs[(size_t)row * 32 + c] = g_dinv[row] * acc;
        __syncthreads();
    }
}

// ---------------- aggregate layer 2 + mean pool (no shared atomics) -------
__global__ void k_agg2(const float* __restrict__ b2) {
    __shared__ float sp[8][32];
    int t = threadIdx.x;
    int warp = t >> 5, lane = t & 31;
    int gw = (blockIdx.x * blockDim.x + t) >> 5;
    float val = 0.f;
    if (gw < N_NODES) {
        int start = g_rowstart[gw];
        int cnt   = g_cnt[gw];
        float a = g_hs[(size_t)gw * 32 + lane];      // self loop
        for (int e = 0; e < cnt; e++) {
            int j = g_col[start + e];
            a += __ldg(&g_hs[(size_t)j * 32 + lane]);
        }
        val = fmaf(g_dinv[gw], a, b2[lane]);
    }
    sp[warp][lane] = val;
    __syncthreads();
    if (warp == 0) {
        float s = 0.f;
        #pragma unroll
        for (int w = 0; w < 8; w++) s += sp[w][lane];
        atomicAdd(&g_pool[lane], s);
    }
}

// ---------------- mean + log_softmax ----------------
__global__ void k_finalize(float* __restrict__ out) {
    int t = threadIdx.x;   // 32 threads, 1 warp
    float p = g_pool[t] * (1.0f / (float)N_NODES);
    float m = p;
    #pragma unroll
    for (int o = 16; o; o >>= 1) m = fmaxf(m, __shfl_xor_sync(0xffffffffu, m, o));
    float e = expf(p - m);
    float s = e;
    #pragma unroll
    for (int o = 16; o; o >>= 1) s += __shfl_xor_sync(0xffffffffu, s, o);
    out[t] = p - m - logf(s);
}

// ---------------- launcher ----------------
extern "C" void kernel_launch(void* const* d_in, const int* in_sizes, int n_in,
                              void* d_out, int out_size) {
    const float* x  = (const float*)d_in[0];
    const void*  ei = d_in[1];                 // int32 or int64, sniffed on device
    const float* W1 = (const float*)d_in[2];
    const float* b1 = (const float*)d_in[3];
    const float* W2 = (const float*)d_in[4];
    const float* b2 = (const float*)d_in[5];
    float*       out = (float*)d_out;

    k_detect<<<1, 32>>>((const unsigned int*)ei);
    k_zero<<<(N_NODES + 255) / 256, 256>>>();
    k_count<<<(N_EDGES + 255) / 256, 256>>>(ei);
    k_scan_partial<<<NCHUNK, SCAN_B>>>();
    k_scan_bsum<<<1, 32>>>();
    k_scan_add<<<(N_NODES + 255) / 256, 256>>>();
    k_place<<<(N_EDGES + 255) / 256, 256>>>(ei);

    k_gemm1<<<1184, 256>>>(x, W1);
    k_agg1<<<(N_NODES * 32 + 255) / 256, 256>>>(b1);
    k_gemm2<<<1184, 256>>>(W2);
    k_agg2<<<(N_NODES * 32 + 255) / 256, 256>>>(b2);
    k_finalize<<<1, 32>>>(out);
}

// round 7
// speedup vs baseline: 1.3129x; 1.3129x over previous
#include <cuda_runtime.h>

#define N_NODES 100000
#define N_EDGES 1600000
#define F_IN  64
#define F_HID 64
#define F_OUT 32
#define SCAN_B 1024
#define NCHUNK ((N_NODES + SCAN_B - 1) / SCAN_B)
#define FULLM 0xffffffffu

// ---------------- scratch (static device globals; no runtime allocation) ---
__device__ int   g_is64;                // 1 if edge_index is int64, 0 if int32
__device__ int   g_cnt[N_NODES];        // in-degree (w/o self loop)
__device__ int   g_rowstart[N_NODES];   // CSR row offsets
__device__ int   g_cursor[N_NODES];     // placement cursors
__device__ int   g_col[N_EDGES];        // CSR column (src) indices
__device__ int   g_src32[N_EDGES];      // int32-converted edge src
__device__ int   g_dst32[N_EDGES];      // int32-converted edge dst
__device__ int   g_bsum[NCHUNK];        // scan block partials
__device__ float g_dinv[N_NODES];       // deg^{-1/2}
// xs / h stored PERMUTED: feature f at byte position ((f&31)*2 + (f>>5));
// lane l reads float2 = features (l, l+32)
__device__ float g_xs[(size_t)N_NODES * F_HID];
__device__ float g_h [(size_t)N_NODES * F_HID];
__device__ float g_hs[(size_t)N_NODES * F_OUT];  // row-major [N,32]
__device__ float g_pool[F_OUT];

// ---------------- dtype sniff: int64 edge_index has zero odd 32-bit words --
__global__ void k_detect(const unsigned int* __restrict__ e) {
    unsigned int acc = 0;
    for (int i = threadIdx.x; i < 2048; i += 32)
        if (i & 1) acc |= e[i];
    #pragma unroll
    for (int o = 16; o; o >>= 1) acc |= __shfl_xor_sync(FULLM, acc, o);
    if (threadIdx.x == 0) g_is64 = (acc == 0u) ? 1 : 0;
}

// ---------------- init ----------------
__global__ void k_zero() {
    int i = blockIdx.x * blockDim.x + threadIdx.x;
    if (i < N_NODES) g_cnt[i] = 0;
    if (i < F_OUT)   g_pool[i] = 0.f;
}

// ---------------- degree count + int32 conversion ----------------
__global__ void k_count(const void* __restrict__ eiv) {
    int e = blockIdx.x * blockDim.x + threadIdx.x;
    if (e >= N_EDGES) return;
    int s, d;
    if (g_is64) {
        s = (int)((const long long*)eiv)[e];
        d = (int)((const long long*)eiv)[N_EDGES + e];
    } else {
        s = ((const int*)eiv)[e];
        d = ((const int*)eiv)[N_EDGES + e];
    }
    g_src32[e] = s;
    g_dst32[e] = d;
    atomicAdd(&g_cnt[d], 1);
}

// ---------------- exclusive scan: int4 + warp shuffles ----------------
__global__ void k_scan_partial() {
    __shared__ int wsum[8];
    int t = threadIdx.x;
    int lane = t & 31, w = t >> 5;
    int gi = blockIdx.x * 256 + t;                  // int4 index
    int4 v = make_int4(0, 0, 0, 0);
    if (gi < N_NODES / 4) v = ((const int4*)g_cnt)[gi];
    int p0 = v.x, p1 = p0 + v.y, p2 = p1 + v.z, p3 = p2 + v.w;
    int tsum = p3;
    int incl = tsum;
    #pragma unroll
    for (int o = 1; o < 32; o <<= 1) {
        int n = __shfl_up_sync(FULLM, incl, o);
        if (lane >= o) incl += n;
    }
    if (lane == 31) wsum[w] = incl;
    __syncthreads();
    if (w == 0) {
        int s = (lane < 8) ? wsum[lane] : 0;
        #pragma unroll
        for (int o = 1; o < 8; o <<= 1) {
            int n = __shfl_up_sync(FULLM, s, o);
            if (lane >= o) s += n;
        }
        if (lane < 8) wsum[lane] = s;               // inclusive warp sums
    }
    __syncthreads();
    int base = (w > 0 ? wsum[w - 1] : 0) + (incl - tsum);
    if (gi < N_NODES / 4)
        ((int4*)g_rowstart)[gi] = make_int4(base, base + p0, base + p1, base + p2);
    if (t == 0) g_bsum[blockIdx.x] = wsum[7];
}

__global__ void k_scan_bsum() {
    int lane = threadIdx.x;
    int carry = 0;
    for (int b = 0; b < NCHUNK; b += 32) {
        int i = b + lane;
        int v = (i < NCHUNK) ? g_bsum[i] : 0;
        int incl = v;
        #pragma unroll
        for (int o = 1; o < 32; o <<= 1) {
            int n = __shfl_up_sync(FULLM, incl, o);
            if (lane >= o) incl += n;
        }
        if (i < NCHUNK) g_bsum[i] = incl - v + carry;
        carry += __shfl_sync(FULLM, incl, 31);
    }
}

__global__ void k_scan_add() {
    int i = blockIdx.x * blockDim.x + threadIdx.x;
    if (i >= N_NODES) return;
    int rs = g_rowstart[i] + g_bsum[i >> 10];
    g_rowstart[i] = rs;
    g_cursor[i]   = rs;
    g_dinv[i] = rsqrtf((float)(g_cnt[i] + 1));       // +1 self loop
}

// ---------------- CSR placement (int32 inputs) ----------------
__global__ void k_place() {
    int e = blockIdx.x * blockDim.x + threadIdx.x;
    if (e >= N_EDGES) return;
    int s = g_src32[e];
    int d = g_dst32[e];
    int pos = atomicAdd(&g_cursor[d], 1);
    g_col[pos] = s;
}

// ---------------- GEMM1: xs = dinv*(x@W1), permuted output ---------------
// tile 32 rows x 64 cols; thread: 2 rows x 4 cols (8 acc). N_NODES%32==0.
__global__ void k_gemm1(const float* __restrict__ x, const float* __restrict__ W1) {
    __shared__ float Ws[64 * 64];
    __shared__ float Xs[32][64];
    int t = threadIdx.x;
    for (int i = t; i < 64 * 64; i += 256) Ws[i] = W1[i];
    int c4 = t & 15;           // cols 4*c4 .. 4*c4+3
    int r  = t >> 4;           // rows r, r+16
    int ntiles = N_NODES / 32;
    for (int tile = blockIdx.x; tile < ntiles; tile += gridDim.x) {
        int row0 = tile * 32;
        const float4* xr = (const float4*)(x + (size_t)row0 * 64);
        __syncthreads();
        #pragma unroll
        for (int i = t; i < 512; i += 256) {
            int rr = i >> 4, qq = i & 15;
            ((float4*)&Xs[rr][0])[qq] = xr[rr * 16 + qq];
        }
        __syncthreads();
        float a0[4] = {0, 0, 0, 0}, a1[4] = {0, 0, 0, 0};
        #pragma unroll
        for (int k = 0; k < 64; k++) {
            float xa = Xs[r][k], xb = Xs[r + 16][k];
            float4 wv = ((const float4*)&Ws[k * 64])[c4];
            a0[0] = fmaf(xa, wv.x, a0[0]); a0[1] = fmaf(xa, wv.y, a0[1]);
            a0[2] = fmaf(xa, wv.z, a0[2]); a0[3] = fmaf(xa, wv.w, a0[3]);
            a1[0] = fmaf(xb, wv.x, a1[0]); a1[1] = fmaf(xb, wv.y, a1[1]);
            a1[2] = fmaf(xb, wv.z, a1[2]); a1[3] = fmaf(xb, wv.w, a1[3]);
        }
        int rowA = row0 + r, rowB = row0 + r + 16;
        float da = g_dinv[rowA], db = g_dinv[rowB];
        #pragma unroll
        for (int q = 0; q < 4; q++) {
            int col = 4 * c4 + q;
            int p = ((col & 31) << 1) | (col >> 5);
            g_xs[(size_t)rowA * 64 + p] = da * a0[q];
            g_xs[(size_t)rowB * 64 + p] = db * a1[q];
        }
    }
}

// ---------------- aggregate layer 1: warp/node, coop cols, float2 --------
__global__ void k_agg1(const float* __restrict__ b1) {
    int gw = (blockIdx.x * blockDim.x + threadIdx.x) >> 5;
    if (gw >= N_NODES) return;
    int lane = threadIdx.x & 31;
    const float2* xs2 = (const float2*)g_xs;
    int start = g_rowstart[gw];
    int cnt   = g_cnt[gw];
    float2 self = xs2[(size_t)gw * 32 + lane];
    float ax = self.x, ay = self.y;
    for (int base = 0; base < cnt; base += 32) {
        int idx = base + lane;
        int j = (idx < cnt) ? g_col[start + idx] : 0;
        int m = min(32, cnt - base);
        int k = 0;
        for (; k + 4 <= m; k += 4) {
            int j0 = __shfl_sync(FULLM, j, k);
            int j1 = __shfl_sync(FULLM, j, k + 1);
            int j2 = __shfl_sync(FULLM, j, k + 2);
            int j3 = __shfl_sync(FULLM, j, k + 3);
            float2 v0 = __ldg(&xs2[(size_t)j0 * 32 + lane]);
            float2 v1 = __ldg(&xs2[(size_t)j1 * 32 + lane]);
            float2 v2 = __ldg(&xs2[(size_t)j2 * 32 + lane]);
            float2 v3 = __ldg(&xs2[(size_t)j3 * 32 + lane]);
            ax += (v0.x + v1.x) + (v2.x + v3.x);
            ay += (v0.y + v1.y) + (v2.y + v3.y);
        }
        for (; k < m; k++) {
            int jj = __shfl_sync(FULLM, j, k);
            float2 v = __ldg(&xs2[(size_t)jj * 32 + lane]);
            ax += v.x; ay += v.y;
        }
    }
    float di = g_dinv[gw];
    float2 o;
    o.x = fmaxf(fmaf(di, ax, b1[lane]),      0.f);
    o.y = fmaxf(fmaf(di, ay, b1[lane + 32]), 0.f);
    ((float2*)g_h)[(size_t)gw * 32 + lane] = o;
}

// ---------------- GEMM2: hs = dinv*(h@W2) [N,64]@[64,32] -----------------
// tile 64 rows x 32 cols; thread: 2 rows x 4 cols.
__global__ void k_gemm2(const float* __restrict__ W2) {
    __shared__ float Ws[64 * 32];
    __shared__ float Hs[64][64];
    int t = threadIdx.x;
    for (int i = t; i < 64 * 32; i += 256) Ws[i] = W2[i];
    int c4 = t & 7;            // cols 4*c4 .. 4*c4+3
    int r  = t >> 3;           // rows r, r+32
    int ntiles = (N_NODES + 63) / 64;
    const float2* h2 = (const float2*)g_h;
    for (int tile = blockIdx.x; tile < ntiles; tile += gridDim.x) {
        int row0 = tile * 64;
        __syncthreads();
        #pragma unroll
        for (int i = t; i < 2048; i += 256) {
            int rr = i >> 5, l = i & 31;
            int row = row0 + rr;
            float2 v = make_float2(0.f, 0.f);
            if (row < N_NODES) v = h2[(size_t)row * 32 + l];
            Hs[rr][l]      = v.x;     // feature l
            Hs[rr][l + 32] = v.y;     // feature l+32
        }
        __syncthreads();
        float a0[4] = {0, 0, 0, 0}, a1[4] = {0, 0, 0, 0};
        #pragma unroll
        for (int k = 0; k < 64; k++) {
            float ha = Hs[r][k], hb = Hs[r + 32][k];
            float4 wv = ((const float4*)&Ws[k * 32])[c4];
            a0[0] = fmaf(ha, wv.x, a0[0]); a0[1] = fmaf(ha, wv.y, a0[1]);
            a0[2] = fmaf(ha, wv.z, a0[2]); a0[3] = fmaf(ha, wv.w, a0[3]);
            a1[0] = fmaf(hb, wv.x, a1[0]); a1[1] = fmaf(hb, wv.y, a1[1]);
            a1[2] = fmaf(hb, wv.z, a1[2]); a1[3] = fmaf(hb, wv.w, a1[3]);
        }
        int rowA = row0 + r, rowB = row0 + r + 32;
        if (rowA < N_NODES) {
            float da = g_dinv[rowA];
            float4 s = make_float4(da * a0[0], da * a0[1], da * a0[2], da * a0[3]);
            *(float4*)&g_hs[(size_t)rowA * 32 + 4 * c4] = s;
        }
        if (rowB < N_NODES) {
            float db = g_dinv[rowB];
            float4 s = make_float4(db * a1[0], db * a1[1], db * a1[2], db * a1[3]);
            *(float4*)&g_hs[(size_t)rowB * 32 + 4 * c4] = s;
        }
    }
}

// ---------------- aggregate layer 2 + mean pool ----------------
__global__ void k_agg2(const float* __restrict__ b2) {
    __shared__ float sp[8][32];
    int t = threadIdx.x;
    int warp = t >> 5, lane = t & 31;
    int gw = (blockIdx.x * blockDim.x + t) >> 5;
    float val = 0.f;
    if (gw < N_NODES) {
        int start = g_rowstart[gw];
        int cnt   = g_cnt[gw];
        float a = g_hs[(size_t)gw * 32 + lane];      // self loop
        for (int base = 0; base < cnt; base += 32) {
            int idx = base + lane;
            int j = (idx < cnt) ? g_col[start + idx] : 0;
            int m = min(32, cnt - base);
            int k = 0;
            for (; k + 4 <= m; k += 4) {
                int j0 = __shfl_sync(FULLM, j, k);
                int j1 = __shfl_sync(FULLM, j, k + 1);
                int j2 = __shfl_sync(FULLM, j, k + 2);
                int j3 = __shfl_sync(FULLM, j, k + 3);
                float v0 = __ldg(&g_hs[(size_t)j0 * 32 + lane]);
                float v1 = __ldg(&g_hs[(size_t)j1 * 32 + lane]);
                float v2 = __ldg(&g_hs[(size_t)j2 * 32 + lane]);
                float v3 = __ldg(&g_hs[(size_t)j3 * 32 + lane]);
                a += (v0 + v1) + (v2 + v3);
            }
            for (; k < m; k++) {
                int jj = __shfl_sync(FULLM, j, k);
                a += __ldg(&g_hs[(size_t)jj * 32 + lane]);
            }
        }
        val = fmaf(g_dinv[gw], a, b2[lane]);
    }
    sp[warp][lane] = val;
    __syncthreads();
    if (warp == 0) {
        float s = 0.f;
        #pragma unroll
        for (int w = 0; w < 8; w++) s += sp[w][lane];
        atomicAdd(&g_pool[lane], s);
    }
}

// ---------------- mean + log_softmax ----------------
__global__ void k_finalize(float* __restrict__ out) {
    int t = threadIdx.x;   // 32 threads, 1 warp
    float p = g_pool[t] * (1.0f / (float)N_NODES);
    float m = p;
    #pragma unroll
    for (int o = 16; o; o >>= 1) m = fmaxf(m, __shfl_xor_sync(FULLM, m, o));
    float e = expf(p - m);
    float s = e;
    #pragma unroll
    for (int o = 16; o; o >>= 1) s += __shfl_xor_sync(FULLM, s, o);
    out[t] = p - m - logf(s);
}

// ---------------- launcher ----------------
extern "C" void kernel_launch(void* const* d_in, const int* in_sizes, int n_in,
                              void* d_out, int out_size) {
    const float* x  = (const float*)d_in[0];
    const void*  ei = d_in[1];                 // int32 or int64, sniffed on device
    const float* W1 = (const float*)d_in[2];
    const float* b1 = (const float*)d_in[3];
    const float* W2 = (const float*)d_in[4];
    const float* b2 = (const float*)d_in[5];
    float*       out = (float*)d_out;

    k_detect<<<1, 32>>>((const unsigned int*)ei);
    k_zero<<<(N_NODES + 255) / 256, 256>>>();
    k_count<<<(N_EDGES + 255) / 256, 256>>>(ei);
    k_scan_partial<<<NCHUNK, 256>>>();
    k_scan_bsum<<<1, 32>>>();
    k_scan_add<<<(N_NODES + 255) / 256, 256>>>();
    k_place<<<(N_EDGES + 255) / 256, 256>>>();

    k_gemm1<<<N_NODES / 32, 256>>>(x, W1);
    k_agg1<<<(N_NODES * 32 + 255) / 256, 256>>>(b1);
    k_gemm2<<<(N_NODES + 63) / 64, 256>>>(W2);
    k_agg2<<<(N_NODES * 32 + 255) / 256, 256>>>(b2);
    k_finalize<<<1, 32>>>(out);
}

// round 8
// speedup vs baseline: 1.9498x; 1.4851x over previous
#include <cuda_runtime.h>
#include <cuda_fp16.h>

#define N_NODES 100000
#define N_EDGES 1600000
#define F_HID 64
#define F_OUT 32
#define SCAN_B 1024
#define NCHUNK ((N_NODES + SCAN_B - 1) / SCAN_B)
#define NPART 12500                       // agg1 grid (= N_NODES/8)
#define FULLM 0xffffffffu

// ---------------- scratch (static device globals) ----------------
__device__ int    g_is64;
__device__ int    g_cnt[N_NODES];         // in-degree (w/o self loop)
__device__ int    g_rowstart[N_NODES];
__device__ int    g_cursor[N_NODES];
__device__ int    g_col[N_EDGES];
__device__ int    g_bsum[NCHUNK];
__device__ float  g_dinv[N_NODES];        // deg^{-1/2}
__device__ float  g_w[N_NODES];           // sum over out-edges of dinv[dst]
__device__ __half g_xsh[(size_t)N_NODES * F_HID];   // fp16 dinv*(x@W1)
__device__ float  g_partial[F_HID * NPART];          // per-block v partials
__device__ float  g_v[F_HID];             // v = sum_j coef_j * h_j

// ---------------- dtype sniff ----------------
__global__ void k_detect(const unsigned int* __restrict__ e) {
    unsigned int acc = 0;
    for (int i = threadIdx.x; i < 2048; i += 32)
        if (i & 1) acc |= e[i];
    #pragma unroll
    for (int o = 16; o; o >>= 1) acc |= __shfl_xor_sync(FULLM, acc, o);
    if (threadIdx.x == 0) g_is64 = (acc == 0u) ? 1 : 0;
}

// ---------------- init ----------------
__global__ void k_zero() {
    int i = blockIdx.x * blockDim.x + threadIdx.x;
    if (i < N_NODES) { g_cnt[i] = 0; g_w[i] = 0.f; }
}

// ---------------- degree count over dst ----------------
__global__ void k_count(const void* __restrict__ eiv) {
    int e = blockIdx.x * blockDim.x + threadIdx.x;
    if (e >= N_EDGES) return;
    int d;
    if (g_is64) d = (int)((const long long*)eiv)[N_EDGES + e];
    else        d = ((const int*)eiv)[N_EDGES + e];
    atomicAdd(&g_cnt[d], 1);
}

// ---------------- exclusive scan (int4 + warp shuffles) ----------------
__global__ void k_scan_partial() {
    __shared__ int wsum[8];
    int t = threadIdx.x;
    int lane = t & 31, w = t >> 5;
    int gi = blockIdx.x * 256 + t;
    int4 v = make_int4(0, 0, 0, 0);
    if (gi < N_NODES / 4) v = ((const int4*)g_cnt)[gi];
    int p0 = v.x, p1 = p0 + v.y, p2 = p1 + v.z, p3 = p2 + v.w;
    int tsum = p3;
    int incl = tsum;
    #pragma unroll
    for (int o = 1; o < 32; o <<= 1) {
        int n = __shfl_up_sync(FULLM, incl, o);
        if (lane >= o) incl += n;
    }
    if (lane == 31) wsum[w] = incl;
    __syncthreads();
    if (w == 0) {
        int s = (lane < 8) ? wsum[lane] : 0;
        #pragma unroll
        for (int o = 1; o < 8; o <<= 1) {
            int n = __shfl_up_sync(FULLM, s, o);
            if (lane >= o) s += n;
        }
        if (lane < 8) wsum[lane] = s;
    }
    __syncthreads();
    int base = (w > 0 ? wsum[w - 1] : 0) + (incl - tsum);
    if (gi < N_NODES / 4)
        ((int4*)g_rowstart)[gi] = make_int4(base, base + p0, base + p1, base + p2);
    if (t == 0) g_bsum[blockIdx.x] = wsum[7];
}

__global__ void k_scan_bsum() {
    int lane = threadIdx.x;
    int carry = 0;
    for (int b = 0; b < NCHUNK; b += 32) {
        int i = b + lane;
        int v = (i < NCHUNK) ? g_bsum[i] : 0;
        int incl = v;
        #pragma unroll
        for (int o = 1; o < 32; o <<= 1) {
            int n = __shfl_up_sync(FULLM, incl, o);
            if (lane >= o) incl += n;
        }
        if (i < NCHUNK) g_bsum[i] = incl - v + carry;
        carry += __shfl_sync(FULLM, incl, 31);
    }
}

__global__ void k_scan_add() {
    int i = blockIdx.x * blockDim.x + threadIdx.x;
    if (i >= N_NODES) return;
    int rs = g_rowstart[i] + g_bsum[i >> 10];
    g_rowstart[i] = rs;
    g_cursor[i]   = rs;
    g_dinv[i] = rsqrtf((float)(g_cnt[i] + 1));
}

// ---------------- CSR placement + w scatter ----------------
__global__ void k_place(const void* __restrict__ eiv) {
    int e = blockIdx.x * blockDim.x + threadIdx.x;
    if (e >= N_EDGES) return;
    int s, d;
    if (g_is64) {
        s = (int)((const long long*)eiv)[e];
        d = (int)((const long long*)eiv)[N_EDGES + e];
    } else {
        s = ((const int*)eiv)[e];
        d = ((const int*)eiv)[N_EDGES + e];
    }
    int pos = atomicAdd(&g_cursor[d], 1);
    g_col[pos] = s;
    atomicAdd(&g_w[s], g_dinv[d]);        // w[src] += dinv[dst]
}

// ---------------- GEMM1: xsh = fp16(dinv*(x@W1)) ----------------
// tile 32 rows x 64 cols; thread: 2 rows x 4 cols. N_NODES%32==0.
__global__ void k_gemm1(const float* __restrict__ x, const float* __restrict__ W1) {
    __shared__ float Ws[64 * 64];
    __shared__ float Xs[32][64];
    int t = threadIdx.x;
    for (int i = t; i < 64 * 64; i += 256) Ws[i] = W1[i];
    int c4 = t & 15;           // cols 4*c4 .. 4*c4+3
    int r  = t >> 4;           // rows r, r+16
    int ntiles = N_NODES / 32;
    for (int tile = blockIdx.x; tile < ntiles; tile += gridDim.x) {
        int row0 = tile * 32;
        const float4* xr = (const float4*)(x + (size_t)row0 * 64);
        __syncthreads();
        #pragma unroll
        for (int i = t; i < 512; i += 256) {
            int rr = i >> 4, qq = i & 15;
            ((float4*)&Xs[rr][0])[qq] = xr[rr * 16 + qq];
        }
        __syncthreads();
        float a0[4] = {0, 0, 0, 0}, a1[4] = {0, 0, 0, 0};
        #pragma unroll
        for (int k = 0; k < 64; k++) {
            float xa = Xs[r][k], xb = Xs[r + 16][k];
            float4 wv = ((const float4*)&Ws[k * 64])[c4];
            a0[0] = fmaf(xa, wv.x, a0[0]); a0[1] = fmaf(xa, wv.y, a0[1]);
            a0[2] = fmaf(xa, wv.z, a0[2]); a0[3] = fmaf(xa, wv.w, a0[3]);
            a1[0] = fmaf(xb, wv.x, a1[0]); a1[1] = fmaf(xb, wv.y, a1[1]);
            a1[2] = fmaf(xb, wv.z, a1[2]); a1[3] = fmaf(xb, wv.w, a1[3]);
        }
        int rowA = row0 + r, rowB = row0 + r + 16;
        float da = g_dinv[rowA], db = g_dinv[rowB];
        __half2* oa = (__half2*)(g_xsh + (size_t)rowA * 64);
        __half2* ob = (__half2*)(g_xsh + (size_t)rowB * 64);
        oa[2 * c4]     = __floats2half2_rn(da * a0[0], da * a0[1]);
        oa[2 * c4 + 1] = __floats2half2_rn(da * a0[2], da * a0[3]);
        ob[2 * c4]     = __floats2half2_rn(db * a1[0], db * a1[1]);
        ob[2 * c4 + 1] = __floats2half2_rn(db * a1[2], db * a1[3]);
    }
}

// ---------------- fused: layer-1 aggregate + relu + weighted v-partials ---
// warp per node; lane l owns features (2l, 2l+1) via one half2 per neighbor.
__global__ void __launch_bounds__(256) k_agg1(const float* __restrict__ b1) {
    __shared__ float sp[8][64];
    int t = threadIdx.x;
    int warp = t >> 5, lane = t & 31;
    int gw = blockIdx.x * 8 + warp;       // grid = NPART, all gw < N_NODES
    const __half2* xs2 = (const __half2*)g_xsh;
    int start = g_rowstart[gw];
    int cnt   = g_cnt[gw];
    float2 self = __half22float2(xs2[(size_t)gw * 32 + lane]);
    float ax = self.x, ay = self.y;
    for (int base = 0; base < cnt; base += 32) {
        int idx = base + lane;
        int j = (idx < cnt) ? g_col[start + idx] : 0;
        int m = min(32, cnt - base);
        int k = 0;
        for (; k + 4 <= m; k += 4) {
            int j0 = __shfl_sync(FULLM, j, k);
            int j1 = __shfl_sync(FULLM, j, k + 1);
            int j2 = __shfl_sync(FULLM, j, k + 2);
            int j3 = __shfl_sync(FULLM, j, k + 3);
            float2 v0 = __half22float2(__ldg(&xs2[(size_t)j0 * 32 + lane]));
            float2 v1 = __half22float2(__ldg(&xs2[(size_t)j1 * 32 + lane]));
            float2 v2 = __half22float2(__ldg(&xs2[(size_t)j2 * 32 + lane]));
            float2 v3 = __half22float2(__ldg(&xs2[(size_t)j3 * 32 + lane]));
            ax += (v0.x + v1.x) + (v2.x + v3.x);
            ay += (v0.y + v1.y) + (v2.y + v3.y);
        }
        for (; k < m; k++) {
            int jj = __shfl_sync(FULLM, j, k);
            float2 v = __half22float2(__ldg(&xs2[(size_t)jj * 32 + lane]));
            ax += v.x; ay += v.y;
        }
    }
    float di = g_dinv[gw];
    float h0 = fmaxf(fmaf(di, ax, b1[2 * lane]),     0.f);
    float h1 = fmaxf(fmaf(di, ay, b1[2 * lane + 1]), 0.f);
    float coef = di * (di + g_w[gw]);     // dinv*(dinv + w): layer-2 pooling weight
    sp[warp][2 * lane]     = coef * h0;
    sp[warp][2 * lane + 1] = coef * h1;
    __syncthreads();
    if (t < 64) {
        float s = 0.f;
        #pragma unroll
        for (int w = 0; w < 8; w++) s += sp[w][t];
        g_partial[(size_t)t * NPART + blockIdx.x] = s;
    }
}

// ---------------- reduce partials: v[f] = sum_b partial[f][b] -------------
__global__ void k_vred() {
    __shared__ float sh[8];
    int f = blockIdx.x, t = threadIdx.x;
    int lane = t & 31, w = t >> 5;
    float s = 0.f;
    for (int i = t; i < NPART; i += 256) s += g_partial[(size_t)f * NPART + i];
    #pragma unroll
    for (int o = 16; o; o >>= 1) s += __shfl_xor_sync(FULLM, s, o);
    if (lane == 0) sh[w] = s;
    __syncthreads();
    if (t == 0) {
        float tot = 0.f;
        #pragma unroll
        for (int i = 0; i < 8; i++) tot += sh[i];
        g_v[f] = tot;
    }
}

// ---------------- final: pooled = v@W2/N + b2, log_softmax ----------------
__global__ void k_fin(const float* __restrict__ W2, const float* __restrict__ b2,
                      float* __restrict__ out) {
    int c = threadIdx.x;   // 32 threads
    float acc = 0.f;
    #pragma unroll
    for (int k = 0; k < 64; k++)
        acc = fmaf(g_v[k], __ldg(&W2[k * 32 + c]), acc);
    float p = acc * (1.0f / (float)N_NODES) + b2[c];
    float m = p;
    #pragma unroll
    for (int o = 16; o; o >>= 1) m = fmaxf(m, __shfl_xor_sync(FULLM, m, o));
    float e = expf(p - m);
    float s = e;
    #pragma unroll
    for (int o = 16; o; o >>= 1) s += __shfl_xor_sync(FULLM, s, o);
    out[c] = p - m - logf(s);
}

// ---------------- launcher ----------------
extern "C" void kernel_launch(void* const* d_in, const int* in_sizes, int n_in,
                              void* d_out, int out_size) {
    const float* x  = (const float*)d_in[0];
    const void*  ei = d_in[1];
    const float* W1 = (const float*)d_in[2];
    const float* b1 = (const float*)d_in[3];
    const float* W2 = (const float*)d_in[4];
    const float* b2 = (const float*)d_in[5];
    float*       out = (float*)d_out;

    k_detect<<<1, 32>>>((const unsigned int*)ei);
    k_zero<<<(N_NODES + 255) / 256, 256>>>();
    k_count<<<(N_EDGES + 255) / 256, 256>>>(ei);
    k_scan_partial<<<NCHUNK, 256>>>();
    k_scan_bsum<<<1, 32>>>();
    k_scan_add<<<(N_NODES + 255) / 256, 256>>>();
    k_place<<<(N_EDGES + 255) / 256, 256>>>(ei);

    k_gemm1<<<N_NODES / 32, 256>>>(x, W1);
    k_agg1<<<NPART, 256>>>(b1);
    k_vred<<<F_HID, 256>>>();
    k_fin<<<1, 32>>>(W2, b2, out);
}